// round 4
// baseline (speedup 1.0000x reference)
#include <cuda_runtime.h>
#include <math.h>

// Problem constants
#define NB 8
#define NT 2048
#define ND 1024
#define NH 64
#define SCALE 0.125f            // H^-0.5 = 1/8
#define NTILES (NT / 64)        // 32 tiles per sequence axis

// Scratch (allocation-free: __device__ globals)
__device__ float g_q[NB * NT * NH];
__device__ float g_k[NB * NT * NH];
__device__ float g_v[NB * NT * NH];
__device__ float g_colsum[NB * NT];

// XOR swizzle: buffer[major][minor] with minor ^= (major & 31).
// Makes both the tile-load writes and the inner-loop reads bank-conflict-free.
__device__ __forceinline__ int swz(int major, int minor) {
    return major * 64 + (minor ^ (major & 31));
}

// ---------------------------------------------------------------------------
// Kernel 1: fused projections  q|k|v = x @ [Wq|Wk|Wv]
// M = B*T = 16384, N = 192 (3 heads fused so x is read exactly once), K = 1024
// Block: 64 rows x 192 cols, 256 threads, 8x6 register tile per thread.
// ---------------------------------------------------------------------------
__global__ __launch_bounds__(256) void proj_kernel(
    const float* __restrict__ x, const float* __restrict__ Wq,
    const float* __restrict__ Wk, const float* __restrict__ Wv)
{
    __shared__ float xs[64 * 32];    // [row][kk]
    __shared__ float ws[32 * 192];   // [kk][col]

    const int tid = threadIdx.x;
    const int tx = tid & 31;         // col group: cols tx + 32*j, j=0..5
    const int ty = tid >> 5;         // row group: rows ty + 8*i,  i=0..7
    const int row0 = blockIdx.x * 64;

    float acc[8][6];
#pragma unroll
    for (int i = 0; i < 8; i++)
#pragma unroll
        for (int j = 0; j < 6; j++) acc[i][j] = 0.f;

    for (int k0 = 0; k0 < ND; k0 += 32) {
        __syncthreads();
#pragma unroll
        for (int l = 0; l < 8; l++) {          // 64x32 x-tile
            int idx = tid + l * 256;
            int r = idx >> 5, kk = idx & 31;
            xs[idx] = x[(row0 + r) * ND + k0 + kk];
        }
#pragma unroll
        for (int l = 0; l < 24; l++) {         // 32x192 W-tile (q|k|v fused)
            int idx = tid + l * 256;
            int kk = idx / 192, c = idx - kk * 192;
            const float* W = (c < 64) ? Wq : (c < 128) ? Wk : Wv;
            ws[idx] = W[(k0 + kk) * NH + (c & 63)];
        }
        __syncthreads();
#pragma unroll 4
        for (int kk = 0; kk < 32; kk++) {
            float a[8], b[6];
#pragma unroll
            for (int i = 0; i < 8; i++) a[i] = xs[(ty + 8 * i) * 32 + kk];   // broadcast
#pragma unroll
            for (int j = 0; j < 6; j++) b[j] = ws[kk * 192 + tx + 32 * j];   // conflict-free
#pragma unroll
            for (int i = 0; i < 8; i++)
#pragma unroll
                for (int j = 0; j < 6; j++)
                    acc[i][j] = fmaf(a[i], b[j], acc[i][j]);
        }
    }

#pragma unroll
    for (int j = 0; j < 6; j++) {
        int c = tx + 32 * j;
        float* dst = (c < 64) ? g_q : (c < 128) ? g_k : g_v;
        int h = c & 63;
#pragma unroll
        for (int i = 0; i < 8; i++)
            dst[(row0 + ty + 8 * i) * NH + h] = acc[i][j];
    }
}

// ---------------------------------------------------------------------------
// Kernel 2: transposed-softmax denominators
//   colsum[b][k] = sum_{q >= k} exp(scale * q_vec[q] . k_vec[k])
// Grid (kt, b): each block owns 64 columns exclusively (no atomics ->
// bitwise-deterministic), loops over all q-tiles >= kt (longest blocks launch
// first: kt = blockIdx.x).
// ---------------------------------------------------------------------------
__global__ __launch_bounds__(256) void colsum_kernel() {
    __shared__ float kst[64 * 64];   // swizzled [h][kcol]
    __shared__ float qst[64 * 64];   // swizzled [h][qrow]
    __shared__ float red[16 * 64];

    const int tid = threadIdx.x;
    const int tx = tid & 15;         // cols c = tx + 16*j
    const int ty = tid >> 4;         // rows r = ty + 16*i
    const int kt = blockIdx.x;
    const int b  = blockIdx.y;
    const int k0 = kt * 64;
    const float* qb = g_q + b * NT * NH;
    const float* kb = g_k + b * NT * NH;

#pragma unroll
    for (int l = 0; l < 16; l++) {
        int idx = tid + l * 256;
        int c = idx >> 6, h = idx & 63;
        kst[swz(h, c)] = kb[(k0 + c) * NH + h];
    }

    float csum[4] = {0.f, 0.f, 0.f, 0.f};

    for (int qt = kt; qt < NTILES; qt++) {
        const int q0 = qt * 64;
        __syncthreads();
#pragma unroll
        for (int l = 0; l < 16; l++) {
            int idx = tid + l * 256;
            int r = idx >> 6, h = idx & 63;
            qst[swz(h, r)] = qb[(q0 + r) * NH + h];
        }
        __syncthreads();

        float s[4][4];
#pragma unroll
        for (int i = 0; i < 4; i++)
#pragma unroll
            for (int j = 0; j < 4; j++) s[i][j] = 0.f;

#pragma unroll 8
        for (int h = 0; h < 64; h++) {
            float a[4], bb[4];
#pragma unroll
            for (int i = 0; i < 4; i++) a[i]  = qst[swz(h, ty + 16 * i)];
#pragma unroll
            for (int j = 0; j < 4; j++) bb[j] = kst[swz(h, tx + 16 * j)];
#pragma unroll
            for (int i = 0; i < 4; i++)
#pragma unroll
                for (int j = 0; j < 4; j++)
                    s[i][j] = fmaf(a[i], bb[j], s[i][j]);
        }

#pragma unroll
        for (int i = 0; i < 4; i++) {
            int qg = q0 + ty + 16 * i;
#pragma unroll
            for (int j = 0; j < 4; j++) {
                int kg = k0 + tx + 16 * j;
                float e = (qg >= kg) ? expf(s[i][j] * SCALE) : 0.f;
                csum[j] += e;
            }
        }
    }

    __syncthreads();
#pragma unroll
    for (int j = 0; j < 4; j++)
        red[ty * 64 + tx + 16 * j] = csum[j];
    __syncthreads();
    if (tid < 64) {
        float s = 0.f;
#pragma unroll
        for (int y = 0; y < 16; y++) s += red[y * 64 + tid];
        g_colsum[b * NT + k0 + tid] = s;
    }
}

// ---------------------------------------------------------------------------
// Kernel 3: output
//   out[b][q][h] = sum_{k <= q} (exp(scale * q.k) / colsum[k]) * v[k][h]
// Grid (qt reversed, b). Per k-tile: phase A recomputes the 64x64 score tile,
// turns it into normalized weights in SMEM, phase B does w @ v.
// ---------------------------------------------------------------------------
__global__ __launch_bounds__(256) void out_kernel(float* __restrict__ out) {
    __shared__ float qst[64 * 64];   // swizzled [h][qrow], persistent
    __shared__ float kws[64 * 64];   // phase A: swizzled [h][kcol]; then weights [kcol][qrow] swizzled
    __shared__ float vs [64 * 64];   // [krow][h]

    const int tid = threadIdx.x;
    const int tx = tid & 15;         // h / kcol group
    const int ty = tid >> 4;         // qrow group
    const int qt = (NTILES - 1) - blockIdx.x;   // longest blocks first
    const int b  = blockIdx.y;
    const int q0 = qt * 64;
    const float* qb = g_q + b * NT * NH;
    const float* kb = g_k + b * NT * NH;
    const float* vb = g_v + b * NT * NH;
    const float* cs = g_colsum + b * NT;

#pragma unroll
    for (int l = 0; l < 16; l++) {
        int idx = tid + l * 256;
        int r = idx >> 6, h = idx & 63;
        qst[swz(h, r)] = qb[(q0 + r) * NH + h];
    }

    float acc[4][4];
#pragma unroll
    for (int i = 0; i < 4; i++)
#pragma unroll
        for (int j = 0; j < 4; j++) acc[i][j] = 0.f;

    for (int kt = 0; kt <= qt; kt++) {
        const int k0 = kt * 64;
        __syncthreads();                      // prev-iter reads of kws/vs done
#pragma unroll
        for (int l = 0; l < 16; l++) {
            int idx = tid + l * 256;
            int c = idx >> 6, h = idx & 63;
            kws[swz(h, c)] = kb[(k0 + c) * NH + h];
            vs [c * 64 + h] = vb[(k0 + c) * NH + h];
        }
        __syncthreads();

        // Phase A: score tile s[r][c] = q[r] . k[c]
        float s[4][4];
#pragma unroll
        for (int i = 0; i < 4; i++)
#pragma unroll
            for (int j = 0; j < 4; j++) s[i][j] = 0.f;

#pragma unroll 8
        for (int h = 0; h < 64; h++) {
            float a[4], bb[4];
#pragma unroll
            for (int i = 0; i < 4; i++) a[i]  = qst[swz(h, ty + 16 * i)];
#pragma unroll
            for (int j = 0; j < 4; j++) bb[j] = kws[swz(h, tx + 16 * j)];
#pragma unroll
            for (int i = 0; i < 4; i++)
#pragma unroll
                for (int j = 0; j < 4; j++)
                    s[i][j] = fmaf(a[i], bb[j], s[i][j]);
        }

        float rinv[4];
#pragma unroll
        for (int j = 0; j < 4; j++)
            rinv[j] = 1.f / cs[k0 + tx + 16 * j];

        __syncthreads();                      // all kst reads done, buffer reusable

        // Write normalized weights w[r][c] into kws as [c-major][r] swizzled
#pragma unroll
        for (int i = 0; i < 4; i++) {
            int qg = q0 + ty + 16 * i;
#pragma unroll
            for (int j = 0; j < 4; j++) {
                int kg = k0 + tx + 16 * j;
                float w = (qg >= kg) ? expf(s[i][j] * SCALE) * rinv[j] : 0.f;
                kws[swz(tx + 16 * j, ty + 16 * i)] = w;
            }
        }
        __syncthreads();

        // Phase B: acc += w @ v   (out[r][h] += w[r][kk] * v[kk][h])
#pragma unroll 8
        for (int kk = 0; kk < 64; kk++) {
            float a[4], bb[4];
#pragma unroll
            for (int i = 0; i < 4; i++) a[i]  = kws[swz(kk, ty + 16 * i)];
#pragma unroll
            for (int j = 0; j < 4; j++) bb[j] = vs[kk * 64 + tx + 16 * j];
#pragma unroll
            for (int i = 0; i < 4; i++)
#pragma unroll
                for (int j = 0; j < 4; j++)
                    acc[i][j] = fmaf(a[i], bb[j], acc[i][j]);
        }
    }

#pragma unroll
    for (int i = 0; i < 4; i++)
#pragma unroll
        for (int j = 0; j < 4; j++)
            out[(b * NT + q0 + ty + 16 * i) * NH + tx + 16 * j] = acc[i][j];
}

// ---------------------------------------------------------------------------
// Launch: 3 kernels on the default stream (graph-capturable, allocation-free,
// no atomics anywhere -> bitwise deterministic across replays).
// Input order per metadata: x, Wk, Wq, Wv.
// ---------------------------------------------------------------------------
extern "C" void kernel_launch(void* const* d_in, const int* in_sizes, int n_in,
                              void* d_out, int out_size) {
    const float* x  = (const float*)d_in[0];
    const float* Wk = (const float*)d_in[1];
    const float* Wq = (const float*)d_in[2];
    const float* Wv = (const float*)d_in[3];
    float* out = (float*)d_out;

    proj_kernel<<<(NB * NT) / 64, 256>>>(x, Wq, Wk, Wv);
    colsum_kernel<<<dim3(NTILES, NB), 256>>>();
    out_kernel<<<dim3(NTILES, NB), 256>>>(out);
}

// round 7
// speedup vs baseline: 2.3180x; 2.3180x over previous
#include <cuda_runtime.h>
#include <math.h>

// Problem constants
#define NB 8
#define NT 2048
#define ND 1024
#define NH 64
#define SCALE 0.125f            // H^-0.5 = 1/8
#define NTILES (NT / 64)        // 32 q-tiles (64 rows)
#define KT128  (NT / 128)       // 16 k-tiles (128 cols) for colsum
#define QCHUNK 4                // q-chunks per k-tile (8 q-tiles each)

// Scratch (allocation-free: __device__ globals)
__device__ float g_q[NB * NT * NH];
__device__ float g_k[NB * NT * NH];
__device__ float g_v[NB * NT * NH];
__device__ float g_v2[NB * NT * NH];                  // v * 1/colsum
__device__ float g_part[QCHUNK * NB * NT];            // partial column sums
__device__ float g_pT[(size_t)NB * NT * NT];          // P^T: [b][k][q], 134 MB

// ---------------------------------------------------------------------------
// Kernel 1: fused projections  q|k|v = x @ [Wq|Wk|Wv]   (unchanged: ~86% of
// the fp32 FMA roofline already)
// ---------------------------------------------------------------------------
__global__ __launch_bounds__(256) void proj_kernel(
    const float* __restrict__ x, const float* __restrict__ Wq,
    const float* __restrict__ Wk, const float* __restrict__ Wv)
{
    __shared__ float xs[64 * 32];
    __shared__ float ws[32 * 192];

    const int tid = threadIdx.x;
    const int tx = tid & 31;
    const int ty = tid >> 5;
    const int row0 = blockIdx.x * 64;

    float acc[8][6];
#pragma unroll
    for (int i = 0; i < 8; i++)
#pragma unroll
        for (int j = 0; j < 6; j++) acc[i][j] = 0.f;

    for (int k0 = 0; k0 < ND; k0 += 32) {
        __syncthreads();
#pragma unroll
        for (int l = 0; l < 8; l++) {
            int idx = tid + l * 256;
            int r = idx >> 5, kk = idx & 31;
            xs[idx] = x[(row0 + r) * ND + k0 + kk];
        }
#pragma unroll
        for (int l = 0; l < 24; l++) {
            int idx = tid + l * 256;
            int kk = idx / 192, c = idx - kk * 192;
            const float* W = (c < 64) ? Wq : (c < 128) ? Wk : Wv;
            ws[idx] = W[(k0 + kk) * NH + (c & 63)];
        }
        __syncthreads();
#pragma unroll 4
        for (int kk = 0; kk < 32; kk++) {
            float a[8], b[6];
#pragma unroll
            for (int i = 0; i < 8; i++) a[i] = xs[(ty + 8 * i) * 32 + kk];
#pragma unroll
            for (int j = 0; j < 6; j++) b[j] = ws[kk * 192 + tx + 32 * j];
#pragma unroll
            for (int i = 0; i < 8; i++)
#pragma unroll
                for (int j = 0; j < 6; j++)
                    acc[i][j] = fmaf(a[i], b[j], acc[i][j]);
        }
    }

#pragma unroll
    for (int j = 0; j < 6; j++) {
        int c = tx + 32 * j;
        float* dst = (c < 64) ? g_q : (c < 128) ? g_k : g_v;
        int h = c & 63;
#pragma unroll
        for (int i = 0; i < 8; i++)
            dst[(row0 + ty + 8 * i) * NH + h] = acc[i][j];
    }
}

// ---------------------------------------------------------------------------
// Kernel 2: score tiles + exp, stored TRANSPOSED (g_pT[b][k][q]) + partial
// column sums. Block (kt128, chunk, b): k cols [kt*128, kt*128+128),
// q-tiles [max(8c, 2kt), 8c+8). <=8 tile-steps per block -> balanced.
// Thread tile: 8 k-rows (ty*8+i) x 4 q-cols (tx*4+j); all inner LDS are
// float4, broadcast or 256B-contiguous (conflict-free).
// ---------------------------------------------------------------------------
__global__ __launch_bounds__(256) void colsum_kernel() {
    __shared__ float kst[64][128];   // [h][k]   32 KB
    __shared__ float qst[64][64];    // [h][q]   16 KB (reused as reduce buf)

    const int tid = threadIdx.x;
    const int tx = tid & 15;
    const int ty = tid >> 4;
    const int kt = blockIdx.x;
    const int c  = blockIdx.y;
    const int b  = blockIdx.z;
    const int k0 = kt * 128;

    int qt_begin = 2 * kt; if (8 * c > qt_begin) qt_begin = 8 * c;
    const int qt_end = 8 * c + 8;

    if (qt_begin >= qt_end) {                 // no work: still own the partial
        if (tid < 128) g_part[(c * NB + b) * NT + k0 + tid] = 0.f;
        return;
    }

    // Load K tile once: read coalesced (float4 along h), transpose into smem.
    {
        const float* kb = g_k + (b * NT + k0) * NH;
#pragma unroll
        for (int l = 0; l < 8; l++) {
            int idx4 = tid + l * 256;         // 2048 float4 = 8192 floats
            int k = idx4 >> 4, h0 = (idx4 & 15) * 4;
            float4 v = *(const float4*)(kb + k * NH + h0);
            kst[h0 + 0][k] = v.x; kst[h0 + 1][k] = v.y;
            kst[h0 + 2][k] = v.z; kst[h0 + 3][k] = v.w;
        }
    }

    float csum[8];
#pragma unroll
    for (int i = 0; i < 8; i++) csum[i] = 0.f;

    for (int qt = qt_begin; qt < qt_end; qt++) {
        const int q0 = qt * 64;
        __syncthreads();
        {
            const float* qb = g_q + (b * NT + q0) * NH;
#pragma unroll
            for (int l = 0; l < 4; l++) {
                int idx4 = tid + l * 256;     // 1024 float4 = 4096 floats
                int q = idx4 >> 4, h0 = (idx4 & 15) * 4;
                float4 v = *(const float4*)(qb + q * NH + h0);
                qst[h0 + 0][q] = v.x; qst[h0 + 1][q] = v.y;
                qst[h0 + 2][q] = v.z; qst[h0 + 3][q] = v.w;
            }
        }
        __syncthreads();

        float s[8][4];
#pragma unroll
        for (int i = 0; i < 8; i++)
#pragma unroll
            for (int j = 0; j < 4; j++) s[i][j] = 0.f;

#pragma unroll 8
        for (int h = 0; h < 64; h++) {
            float4 a0 = *(const float4*)&kst[h][ty * 8];      // broadcast
            float4 a1 = *(const float4*)&kst[h][ty * 8 + 4];
            float4 bb = *(const float4*)&qst[h][tx * 4];      // contiguous
            float a[8] = {a0.x, a0.y, a0.z, a0.w, a1.x, a1.y, a1.z, a1.w};
            float bv[4] = {bb.x, bb.y, bb.z, bb.w};
#pragma unroll
            for (int i = 0; i < 8; i++)
#pragma unroll
                for (int j = 0; j < 4; j++)
                    s[i][j] = fmaf(a[i], bv[j], s[i][j]);
        }

        // exp + causal mask, accumulate column sums, store P^T tile
        const bool full = (q0 >= k0 + 128);   // tile entirely unmasked
#pragma unroll
        for (int i = 0; i < 8; i++) {
            const int kg = k0 + ty * 8 + i;
            float4 e;
            float* ep = &e.x;
#pragma unroll
            for (int j = 0; j < 4; j++) {
                int qg = q0 + tx * 4 + j;
                float v = (full || qg >= kg) ? __expf(s[i][j] * SCALE) : 0.f;
                ep[j] = v;
                csum[i] += v;
            }
            *(float4*)(g_pT + ((size_t)(b * NT + kg)) * NT + q0 + tx * 4) = e;
        }
    }

    // Reduce csum over the 16 tx-groups (reuse qst as [16][128] buffer)
    __syncthreads();
    float* red = &qst[0][0];
#pragma unroll
    for (int i = 0; i < 8; i++)
        red[tx * 128 + ty * 8 + i] = csum[i];
    __syncthreads();
    if (tid < 128) {
        float s = 0.f;
#pragma unroll
        for (int x = 0; x < 16; x++) s += red[x * 128 + tid];
        g_part[(c * NB + b) * NT + k0 + tid] = s;
    }
}

// ---------------------------------------------------------------------------
// Kernel 3: v' = v * 1/colsum  (combines the QCHUNK partials; folds the
// softmax denominator into V so the output pass is a pure GEMM)
// ---------------------------------------------------------------------------
__global__ __launch_bounds__(256) void scalev_kernel() {
    int gid = blockIdx.x * 256 + threadIdx.x;        // one float4 each
    int token = gid >> 4;                            // 16 float4 per token
    int h0 = (gid & 15) * 4;
    int b = token >> 11, k = token & 2047;
    float s = g_part[(0 * NB + b) * NT + k] + g_part[(1 * NB + b) * NT + k]
            + g_part[(2 * NB + b) * NT + k] + g_part[(3 * NB + b) * NT + k];
    float rinv = 1.f / s;                            // s > 0 (diagonal term)
    float4 v = *(const float4*)(g_v + token * NH + h0);
    v.x *= rinv; v.y *= rinv; v.z *= rinv; v.w *= rinv;
    *(float4*)(g_v2 + token * NH + h0) = v;
}

// ---------------------------------------------------------------------------
// Kernel 4: out = P_causal @ V'. Both operands k-major in gmem -> direct
// float4 smem stores, zero transposes. Thread tile 4q x 4h, all inner LDS
// are float4 broadcast/contiguous.
// ---------------------------------------------------------------------------
__global__ __launch_bounds__(256) void out_kernel(float* __restrict__ out) {
    __shared__ float ws[64][64];     // P^T tile [kk][q]   16 KB
    __shared__ float vs[64][64];     // V' tile  [kk][h]   16 KB

    const int tid = threadIdx.x;
    const int tx = tid & 15;
    const int ty = tid >> 4;
    const int qt = (NTILES - 1) - blockIdx.x;        // longest blocks first
    const int b  = blockIdx.y;
    const int q0 = qt * 64;

    float acc[4][4];
#pragma unroll
    for (int i = 0; i < 4; i++)
#pragma unroll
        for (int j = 0; j < 4; j++) acc[i][j] = 0.f;

    for (int kt = 0; kt <= qt; kt++) {
        const int k0 = kt * 64;
        __syncthreads();
        {
            const float* pb = g_pT + ((size_t)(b * NT + k0)) * NT + q0;
            const float* vb = g_v2 + (b * NT + k0) * NH;
#pragma unroll
            for (int l = 0; l < 4; l++) {
                int idx4 = tid + l * 256;
                int r = idx4 >> 4, c0 = (idx4 & 15) * 4;
                *(float4*)&ws[r][c0] = *(const float4*)(pb + (size_t)r * NT + c0);
                *(float4*)&vs[r][c0] = *(const float4*)(vb + r * NH + c0);
            }
        }
        __syncthreads();

#pragma unroll 8
        for (int kk = 0; kk < 64; kk++) {
            float4 a  = *(const float4*)&ws[kk][ty * 4];   // broadcast
            float4 bb = *(const float4*)&vs[kk][tx * 4];   // contiguous
            float av[4] = {a.x, a.y, a.z, a.w};
            float bv[4] = {bb.x, bb.y, bb.z, bb.w};
#pragma unroll
            for (int i = 0; i < 4; i++)
#pragma unroll
                for (int j = 0; j < 4; j++)
                    acc[i][j] = fmaf(av[i], bv[j], acc[i][j]);
        }
    }

#pragma unroll
    for (int i = 0; i < 4; i++) {
        float4 v = {acc[i][0], acc[i][1], acc[i][2], acc[i][3]};
        *(float4*)(out + (size_t)(b * NT + q0 + ty * 4 + i) * NH + tx * 4) = v;
    }
}

// ---------------------------------------------------------------------------
// Launch (graph-capturable, allocation-free, atomic-free -> deterministic).
// Input order per metadata: x, Wk, Wq, Wv.
// ---------------------------------------------------------------------------
extern "C" void kernel_launch(void* const* d_in, const int* in_sizes, int n_in,
                              void* d_out, int out_size) {
    const float* x  = (const float*)d_in[0];
    const float* Wk = (const float*)d_in[1];
    const float* Wq = (const float*)d_in[2];
    const float* Wv = (const float*)d_in[3];
    float* out = (float*)d_out;

    proj_kernel<<<(NB * NT) / 64, 256>>>(x, Wq, Wk, Wv);
    colsum_kernel<<<dim3(KT128, QCHUNK, NB), 256>>>();
    scalev_kernel<<<(NB * NT * NH / 4) / 256, 256>>>();
    out_kernel<<<dim3(NTILES, NB), 256>>>(out);
}

// round 9
// speedup vs baseline: 3.2228x; 1.3903x over previous
#include <cuda_runtime.h>
#include <cuda_bf16.h>
#include <math.h>
#include <stdint.h>

// Problem constants
#define NB 8
#define NT 2048
#define ND 1024
#define NH 64
#define SCALE 0.125f            // H^-0.5 = 1/8
#define NTILES (NT / 64)        // 32 q-tiles (64 rows)
#define KT128  (NT / 128)       // 16 k-tiles (128 cols) for colsum
#define QCHUNK 4                // q-chunks per k-tile (8 q-tiles each)

// Scratch (allocation-free: __device__ globals)
__device__ float g_q[NB * NT * NH];
__device__ float g_k[NB * NT * NH];
__device__ float g_v[NB * NT * NH];
__device__ float g_v2[NB * NT * NH];                  // v * 1/colsum
__device__ float g_part[QCHUNK * NB * NT];            // partial column sums
__device__ float g_pT[(size_t)NB * NT * NT];          // P^T: [b][k][q], 134 MB
// W transposed + split: [hilo][mat][n=64][k=1024] bf16 (B operand, k contiguous)
__device__ __nv_bfloat16 g_wb[2 * 3 * 64 * 1024];

// ---------------------------------------------------------------------------
// Helpers: legacy tensor path (compute_103-legal): ldmatrix + mma.sync bf16
// ---------------------------------------------------------------------------
__device__ __forceinline__ uint32_t smem_u32(const void* p) {
    uint32_t a;
    asm("{ .reg .u64 t; cvta.to.shared.u64 t, %1; cvt.u32.u64 %0, t; }"
        : "=r"(a) : "l"(p));
    return a;
}
#define LDSM_X4(r0, r1, r2, r3, a)                                              \
    asm volatile("ldmatrix.sync.aligned.m8n8.x4.shared.b16 {%0,%1,%2,%3}, [%4];" \
                 : "=r"(r0), "=r"(r1), "=r"(r2), "=r"(r3) : "r"(a))
#define LDSM_X2(r0, r1, a)                                                      \
    asm volatile("ldmatrix.sync.aligned.m8n8.x2.shared.b16 {%0,%1}, [%2];"      \
                 : "=r"(r0), "=r"(r1) : "r"(a))
#define MMA_BF16(d, a, b)                                                       \
    asm volatile("mma.sync.aligned.m16n8k16.row.col.f32.bf16.bf16.f32 "         \
                 "{%0,%1,%2,%3}, {%4,%5,%6,%7}, {%8,%9}, {%0,%1,%2,%3};"        \
                 : "+f"((d)[0]), "+f"((d)[1]), "+f"((d)[2]), "+f"((d)[3])       \
                 : "r"((a)[0]), "r"((a)[1]), "r"((a)[2]), "r"((a)[3]),          \
                   "r"((b)[0]), "r"((b)[1]))

// 16B-unit swizzle for 64B rows: slot(r,u) = r*64 + (u ^ ((r>>1)&3))*16.
// ldmatrix 8-row fetch covers all eight 16B slots of a 128B pair -> conflict-free.
__device__ __forceinline__ uint32_t swzA(int r, int u) {
    return (uint32_t)(r * 64 + ((u ^ ((r >> 1) & 3)) << 4));
}

// ---------------------------------------------------------------------------
// Kernel 0: W -> transposed, bf16 hi/lo split, B layout [hilo][mat][n][k].
// 48 blocks: (mat, 64-col k-chunk). smem tile transpose, both sides coalesced.
// ---------------------------------------------------------------------------
__global__ __launch_bounds__(256) void wconv_kernel(
    const float* __restrict__ Wq, const float* __restrict__ Wk,
    const float* __restrict__ Wv)
{
    __shared__ float tile[64 * 65];
    const int mat = blockIdx.x >> 4;
    const int k0  = (blockIdx.x & 15) * 64;
    const float* W = (mat == 0) ? Wq : (mat == 1) ? Wk : Wv;
    const int tid = threadIdx.x;

#pragma unroll
    for (int l = 0; l < 16; l++) {            // read W[k0+k][n], n coalesced
        int idx = tid + l * 256;
        int k = idx >> 6, n = idx & 63;
        tile[k * 65 + n] = W[(k0 + k) * NH + n];
    }
    __syncthreads();
#pragma unroll
    for (int l = 0; l < 16; l++) {            // write [n][k], k coalesced
        int idx = tid + l * 256;
        int n = idx >> 6, k = idx & 63;
        float v = tile[k * 65 + n];
        __nv_bfloat16 h = __float2bfloat16_rn(v);
        __nv_bfloat16 lo = __float2bfloat16_rn(v - __bfloat162float(h));
        g_wb[((0 * 3 + mat) * 64 + n) * 1024 + k0 + k] = h;
        g_wb[((1 * 3 + mat) * 64 + n) * 1024 + k0 + k] = lo;
    }
}

// ---------------------------------------------------------------------------
// Kernel 1: projection GEMM via mma.sync bf16, split-fp32 (3 terms).
// CTA: 128 token rows x 192 cols (q|k|v). 8 warps, warp tile 32x96
// (2 m16-tiles x 12 n8-tiles). K chunks of 32 (2 k16 steps each).
// ---------------------------------------------------------------------------
__global__ __launch_bounds__(256) void projmma_kernel(const float* __restrict__ x)
{
    __shared__ __align__(16) char smA[2][128 * 64];   // [hilo][r=128][64B row]
    __shared__ __align__(16) char smB[2][192 * 64];   // [hilo][rowB=192][64B row]

    const int tid  = threadIdx.x;
    const int wid  = tid >> 5;
    const int lane = tid & 31;
    const int row0 = blockIdx.x * 128;
    const int r0w  = (wid >> 1) * 32;        // warp row base (0/32/64/96)
    const int c0w  = (wid & 1) * 96;         // warp col base (0/96)

    const uint32_t aHiB = smem_u32(smA[0]);
    const uint32_t aLoB = smem_u32(smA[1]);
    const uint32_t bHiB = smem_u32(smB[0]);
    const uint32_t bLoB = smem_u32(smB[1]);

    float acc[2][12][4];
#pragma unroll
    for (int mi = 0; mi < 2; mi++)
#pragma unroll
        for (int ni = 0; ni < 12; ni++)
#pragma unroll
            for (int r = 0; r < 4; r++) acc[mi][ni][r] = 0.f;

    // Per-thread ldmatrix source rows (fixed across chunks)
    const int rA0 = r0w + (lane & 15);        // mi=0 ; mi=1 adds 16
    const int uHiA = lane >> 4;               // +2*s

    for (int c = 0; c < 32; c++) {            // 32 K-chunks of 32
        const int k0 = c * 32;
        __syncthreads();
        // ---- load A chunk: x fp32 -> bf16 hi/lo, swizzled STS ----
#pragma unroll
        for (int l = 0; l < 4; l++) {
            int row = (tid >> 3) + l * 32;
            int kf  = (tid & 7) * 4;
            float4 xv = *(const float4*)(x + (size_t)(row0 + row) * ND + k0 + kf);
            __nv_bfloat162 h01, h23, l01, l23;
            h01.x = __float2bfloat16_rn(xv.x); h01.y = __float2bfloat16_rn(xv.y);
            h23.x = __float2bfloat16_rn(xv.z); h23.y = __float2bfloat16_rn(xv.w);
            l01.x = __float2bfloat16_rn(xv.x - __bfloat162float(h01.x));
            l01.y = __float2bfloat16_rn(xv.y - __bfloat162float(h01.y));
            l23.x = __float2bfloat16_rn(xv.z - __bfloat162float(h23.x));
            l23.y = __float2bfloat16_rn(xv.w - __bfloat162float(h23.y));
            uint32_t off = swzA(row, kf >> 3) + ((kf & 4) ? 8 : 0);
            uint2 hv = { *(uint32_t*)&h01, *(uint32_t*)&h23 };
            uint2 lv = { *(uint32_t*)&l01, *(uint32_t*)&l23 };
            *(uint2*)(smA[0] + off) = hv;
            *(uint2*)(smA[1] + off) = lv;
        }
        // ---- load B chunk: pre-split tiles, LDG.128 -> swizzled STS.128 ----
#pragma unroll
        for (int l = 0; l < 6; l++) {
            int idx = tid + l * 256;          // 1536 x 16B
            int rowhl = idx >> 2;             // 0..383: [hilo*192 + mat*64 + n]
            int seg = idx & 3;
            int hilo = rowhl >= 192;
            int row = rowhl - hilo * 192;
            uint4 v = *(const uint4*)((const char*)g_wb + (size_t)rowhl * 2048 + k0 * 2 + seg * 16);
            *(uint4*)(smB[hilo] + swzA(row, seg)) = v;
        }
        __syncthreads();

        // ---- 2 k16 steps of mma ----
#pragma unroll
        for (int s = 0; s < 2; s++) {
            uint32_t ah[2][4], al[2][4];
#pragma unroll
            for (int mi = 0; mi < 2; mi++) {
                int r = rA0 + mi * 16;
                uint32_t off = swzA(r, 2 * s + uHiA);
                LDSM_X4(ah[mi][0], ah[mi][1], ah[mi][2], ah[mi][3], aHiB + off);
                LDSM_X4(al[mi][0], al[mi][1], al[mi][2], al[mi][3], aLoB + off);
            }
#pragma unroll
            for (int ni = 0; ni < 12; ni++) {
                int rB = c0w + ni * 8 + (lane & 7);
                uint32_t off = swzA(rB, 2 * s + ((lane >> 3) & 1));
                uint32_t bh[2], bl[2];
                LDSM_X2(bh[0], bh[1], bHiB + off);
                LDSM_X2(bl[0], bl[1], bLoB + off);
#pragma unroll
                for (int mi = 0; mi < 2; mi++) {
                    MMA_BF16(acc[mi][ni], ah[mi], bh);   // hi*hi
                    MMA_BF16(acc[mi][ni], ah[mi], bl);   // hi*lo
                    MMA_BF16(acc[mi][ni], al[mi], bh);   // lo*hi
                }
            }
        }
    }

    // ---- epilogue: D frags -> g_q/g_k/g_v (fp32) ----
#pragma unroll
    for (int ni = 0; ni < 12; ni++) {
        int cg = c0w + ni * 8 + (lane & 3) * 2;
        float* dst = (cg < 64) ? g_q : (cg < 128) ? g_k : g_v;
        int h = cg & 63;
#pragma unroll
        for (int mi = 0; mi < 2; mi++) {
            int r = row0 + r0w + mi * 16 + (lane >> 2);
            float2 v0 = {acc[mi][ni][0], acc[mi][ni][1]};
            float2 v1 = {acc[mi][ni][2], acc[mi][ni][3]};
            *(float2*)(dst + (size_t)r * NH + h) = v0;
            *(float2*)(dst + (size_t)(r + 8) * NH + h) = v1;
        }
    }
}

// ---------------------------------------------------------------------------
// Kernel 2: score tiles + exp -> g_pT (transposed) + partial column sums.
// ---------------------------------------------------------------------------
__global__ __launch_bounds__(256) void colsum_kernel() {
    __shared__ float kst[64][128];
    __shared__ float qst[64][64];

    const int tid = threadIdx.x;
    const int tx = tid & 15;
    const int ty = tid >> 4;
    const int kt = blockIdx.x;
    const int c  = blockIdx.y;
    const int b  = blockIdx.z;
    const int k0 = kt * 128;

    int qt_begin = 2 * kt; if (8 * c > qt_begin) qt_begin = 8 * c;
    const int qt_end = 8 * c + 8;

    if (qt_begin >= qt_end) {
        if (tid < 128) g_part[(c * NB + b) * NT + k0 + tid] = 0.f;
        return;
    }

    {
        const float* kb = g_k + (b * NT + k0) * NH;
#pragma unroll
        for (int l = 0; l < 8; l++) {
            int idx4 = tid + l * 256;
            int k = idx4 >> 4, h0 = (idx4 & 15) * 4;
            float4 v = *(const float4*)(kb + k * NH + h0);
            kst[h0 + 0][k] = v.x; kst[h0 + 1][k] = v.y;
            kst[h0 + 2][k] = v.z; kst[h0 + 3][k] = v.w;
        }
    }

    float csum[8];
#pragma unroll
    for (int i = 0; i < 8; i++) csum[i] = 0.f;

    for (int qt = qt_begin; qt < qt_end; qt++) {
        const int q0 = qt * 64;
        __syncthreads();
        {
            const float* qb = g_q + (b * NT + q0) * NH;
#pragma unroll
            for (int l = 0; l < 4; l++) {
                int idx4 = tid + l * 256;
                int q = idx4 >> 4, h0 = (idx4 & 15) * 4;
                float4 v = *(const float4*)(qb + q * NH + h0);
                qst[h0 + 0][q] = v.x; qst[h0 + 1][q] = v.y;
                qst[h0 + 2][q] = v.z; qst[h0 + 3][q] = v.w;
            }
        }
        __syncthreads();

        float s[8][4];
#pragma unroll
        for (int i = 0; i < 8; i++)
#pragma unroll
            for (int j = 0; j < 4; j++) s[i][j] = 0.f;

#pragma unroll 8
        for (int h = 0; h < 64; h++) {
            float4 a0 = *(const float4*)&kst[h][ty * 8];
            float4 a1 = *(const float4*)&kst[h][ty * 8 + 4];
            float4 bb = *(const float4*)&qst[h][tx * 4];
            float a[8] = {a0.x, a0.y, a0.z, a0.w, a1.x, a1.y, a1.z, a1.w};
            float bv[4] = {bb.x, bb.y, bb.z, bb.w};
#pragma unroll
            for (int i = 0; i < 8; i++)
#pragma unroll
                for (int j = 0; j < 4; j++)
                    s[i][j] = fmaf(a[i], bv[j], s[i][j]);
        }

        const bool full = (q0 >= k0 + 128);
#pragma unroll
        for (int i = 0; i < 8; i++) {
            const int kg = k0 + ty * 8 + i;
            float4 e;
            float* ep = &e.x;
#pragma unroll
            for (int j = 0; j < 4; j++) {
                int qg = q0 + tx * 4 + j;
                float v = (full || qg >= kg) ? __expf(s[i][j] * SCALE) : 0.f;
                ep[j] = v;
                csum[i] += v;
            }
            *(float4*)(g_pT + ((size_t)(b * NT + kg)) * NT + q0 + tx * 4) = e;
        }
    }

    __syncthreads();
    float* red = &qst[0][0];
#pragma unroll
    for (int i = 0; i < 8; i++)
        red[tx * 128 + ty * 8 + i] = csum[i];
    __syncthreads();
    if (tid < 128) {
        float s = 0.f;
#pragma unroll
        for (int xg = 0; xg < 16; xg++) s += red[xg * 128 + tid];
        g_part[(c * NB + b) * NT + k0 + tid] = s;
    }
}

// ---------------------------------------------------------------------------
// Kernel 3: v' = v * 1/colsum
// ---------------------------------------------------------------------------
__global__ __launch_bounds__(256) void scalev_kernel() {
    int gid = blockIdx.x * 256 + threadIdx.x;
    int token = gid >> 4;
    int h0 = (gid & 15) * 4;
    int b = token >> 11, k = token & 2047;
    float s = g_part[(0 * NB + b) * NT + k] + g_part[(1 * NB + b) * NT + k]
            + g_part[(2 * NB + b) * NT + k] + g_part[(3 * NB + b) * NT + k];
    float rinv = 1.f / s;
    float4 v = *(const float4*)(g_v + token * NH + h0);
    v.x *= rinv; v.y *= rinv; v.z *= rinv; v.w *= rinv;
    *(float4*)(g_v2 + token * NH + h0) = v;
}

// ---------------------------------------------------------------------------
// Kernel 4: out = P_causal @ V', register-prefetch double-buffered.
// ---------------------------------------------------------------------------
__global__ __launch_bounds__(256) void out_kernel(float* __restrict__ out) {
    __shared__ float ws[64][64];
    __shared__ float vs[64][64];

    const int tid = threadIdx.x;
    const int tx = tid & 15;
    const int ty = tid >> 4;
    const int qt = (NTILES - 1) - blockIdx.x;
    const int b  = blockIdx.y;
    const int q0 = qt * 64;
    const int lr = tid >> 4;
    const int lc = (tid & 15) * 4;

    float acc[4][4];
#pragma unroll
    for (int i = 0; i < 4; i++)
#pragma unroll
        for (int j = 0; j < 4; j++) acc[i][j] = 0.f;

    float4 pw[4], pv[4];
#define LOAD_TILES(KT)                                                          \
    do {                                                                        \
        const float* pb = g_pT + ((size_t)(b * NT + (KT) * 64)) * NT + q0;      \
        const float* vb = g_v2 + (b * NT + (KT) * 64) * NH;                     \
        _Pragma("unroll")                                                       \
        for (int l = 0; l < 4; l++) {                                           \
            pw[l] = *(const float4*)(pb + (size_t)(lr + l * 16) * NT + lc);     \
            pv[l] = *(const float4*)(vb + (lr + l * 16) * NH + lc);             \
        }                                                                       \
    } while (0)

    LOAD_TILES(0);

    for (int kt = 0; kt <= qt; kt++) {
        __syncthreads();
#pragma unroll
        for (int l = 0; l < 4; l++) {
            *(float4*)&ws[lr + l * 16][lc] = pw[l];
            *(float4*)&vs[lr + l * 16][lc] = pv[l];
        }
        __syncthreads();
        if (kt < qt) LOAD_TILES(kt + 1);

#pragma unroll 8
        for (int kk = 0; kk < 64; kk++) {
            float4 a  = *(const float4*)&ws[kk][ty * 4];
            float4 bb = *(const float4*)&vs[kk][tx * 4];
            float av[4] = {a.x, a.y, a.z, a.w};
            float bv[4] = {bb.x, bb.y, bb.z, bb.w};
#pragma unroll
            for (int i = 0; i < 4; i++)
#pragma unroll
                for (int j = 0; j < 4; j++)
                    acc[i][j] = fmaf(av[i], bv[j], acc[i][j]);
        }
    }

#pragma unroll
    for (int i = 0; i < 4; i++) {
        float4 v = {acc[i][0], acc[i][1], acc[i][2], acc[i][3]};
        *(float4*)(out + (size_t)(b * NT + q0 + ty * 4 + i) * NH + tx * 4) = v;
    }
#undef LOAD_TILES
}

// ---------------------------------------------------------------------------
// Launch (graph-capturable, allocation-free, atomic-free -> deterministic).
// Input order per metadata: x, Wk, Wq, Wv.
// ---------------------------------------------------------------------------
extern "C" void kernel_launch(void* const* d_in, const int* in_sizes, int n_in,
                              void* d_out, int out_size) {
    const float* x  = (const float*)d_in[0];
    const float* Wk = (const float*)d_in[1];
    const float* Wq = (const float*)d_in[2];
    const float* Wv = (const float*)d_in[3];
    float* out = (float*)d_out;

    wconv_kernel<<<48, 256>>>(Wq, Wk, Wv);
    projmma_kernel<<<(NB * NT) / 128, 256>>>(x);
    colsum_kernel<<<dim3(KT128, QCHUNK, NB), 256>>>();
    scalev_kernel<<<(NB * NT * NH / 4) / 256, 256>>>();
    out_kernel<<<dim3(NTILES, NB), 256>>>(out);
}

// round 10
// speedup vs baseline: 5.4928x; 1.7043x over previous
#include <cuda_runtime.h>
#include <cuda_bf16.h>
#include <math.h>
#include <stdint.h>

// Problem constants
#define NB 8
#define NT 2048
#define ND 1024
#define NH 64
#define SCALE 0.125f            // H^-0.5 = 1/8
#define NTILES (NT / 64)        // 32 q-tiles (64 rows)
#define KT128  (NT / 128)       // 16 k-tiles (128 cols) for colsum
#define QCHUNK 4                // q-chunks per k-tile (8 q-tiles each)

// Scratch (allocation-free: __device__ globals)
__device__ float g_v[NB * NT * NH];                    // V fp32 (from proj)
__device__ float g_part[QCHUNK * NB * NT];             // partial column sums
__device__ __nv_bfloat16 g_qh[NB * NT * NH];           // Q hi/lo bf16
__device__ __nv_bfloat16 g_ql[NB * NT * NH];
__device__ __nv_bfloat16 g_kh[NB * NT * NH];           // K hi/lo bf16
__device__ __nv_bfloat16 g_kl[NB * NT * NH];
__device__ __nv_bfloat16 g_v2h[NB * NT * NH];          // V' = V/colsum hi/lo
__device__ __nv_bfloat16 g_v2l[NB * NT * NH];
__device__ __nv_bfloat16 g_pTh[(size_t)NB * NT * NT];  // P^T hi: [b][k][q] 67MB
__device__ __nv_bfloat16 g_pTl[(size_t)NB * NT * NT];  // P^T lo
// W transposed + split: [hilo][mat][n=64][k=1024] bf16
__device__ __nv_bfloat16 g_wb[2 * 3 * 64 * 1024];

// ---------------------------------------------------------------------------
// Helpers: legacy tensor path (compute_103-legal): ldmatrix + mma.sync bf16
// ---------------------------------------------------------------------------
__device__ __forceinline__ uint32_t smem_u32(const void* p) {
    uint32_t a;
    asm("{ .reg .u64 t; cvta.to.shared.u64 t, %1; cvt.u32.u64 %0, t; }"
        : "=r"(a) : "l"(p));
    return a;
}
#define LDSM_X4(r0, r1, r2, r3, a)                                              \
    asm volatile("ldmatrix.sync.aligned.m8n8.x4.shared.b16 {%0,%1,%2,%3}, [%4];" \
                 : "=r"(r0), "=r"(r1), "=r"(r2), "=r"(r3) : "r"(a))
#define LDSM_X2(r0, r1, a)                                                      \
    asm volatile("ldmatrix.sync.aligned.m8n8.x2.shared.b16 {%0,%1}, [%2];"      \
                 : "=r"(r0), "=r"(r1) : "r"(a))
#define LDSM_X4_T(r0, r1, r2, r3, a)                                            \
    asm volatile("ldmatrix.sync.aligned.m8n8.x4.trans.shared.b16 {%0,%1,%2,%3}, [%4];" \
                 : "=r"(r0), "=r"(r1), "=r"(r2), "=r"(r3) : "r"(a))
#define LDSM_X2_T(r0, r1, a)                                                    \
    asm volatile("ldmatrix.sync.aligned.m8n8.x2.trans.shared.b16 {%0,%1}, [%2];" \
                 : "=r"(r0), "=r"(r1) : "r"(a))
#define MMA_BF16(d, a, b)                                                       \
    asm volatile("mma.sync.aligned.m16n8k16.row.col.f32.bf16.bf16.f32 "         \
                 "{%0,%1,%2,%3}, {%4,%5,%6,%7}, {%8,%9}, {%0,%1,%2,%3};"        \
                 : "+f"((d)[0]), "+f"((d)[1]), "+f"((d)[2]), "+f"((d)[3])       \
                 : "r"((a)[0]), "r"((a)[1]), "r"((a)[2]), "r"((a)[3]),          \
                   "r"((b)[0]), "r"((b)[1]))

// Swizzles (16B units). 64B rows (proj) / 128B rows (colsum, out).
__device__ __forceinline__ uint32_t swzA(int r, int u) {
    return (uint32_t)(r * 64 + ((u ^ ((r >> 1) & 3)) << 4));
}
__device__ __forceinline__ uint32_t swz128(int r, int u) {
    return (uint32_t)(r * 128 + ((u ^ (r & 7)) << 4));
}
__device__ __forceinline__ void bf16split(float f, __nv_bfloat16& h, __nv_bfloat16& l) {
    h = __float2bfloat16_rn(f);
    l = __float2bfloat16_rn(f - __bfloat162float(h));
}

// ---------------------------------------------------------------------------
// Kernel 0: W -> transposed, bf16 hi/lo split, B layout [hilo][mat][n][k].
// ---------------------------------------------------------------------------
__global__ __launch_bounds__(256) void wconv_kernel(
    const float* __restrict__ Wq, const float* __restrict__ Wk,
    const float* __restrict__ Wv)
{
    __shared__ float tile[64 * 65];
    const int mat = blockIdx.x >> 4;
    const int k0  = (blockIdx.x & 15) * 64;
    const float* W = (mat == 0) ? Wq : (mat == 1) ? Wk : Wv;
    const int tid = threadIdx.x;

#pragma unroll
    for (int l = 0; l < 16; l++) {
        int idx = tid + l * 256;
        int k = idx >> 6, n = idx & 63;
        tile[k * 65 + n] = W[(k0 + k) * NH + n];
    }
    __syncthreads();
#pragma unroll
    for (int l = 0; l < 16; l++) {
        int idx = tid + l * 256;
        int n = idx >> 6, k = idx & 63;
        __nv_bfloat16 h, lo;
        bf16split(tile[k * 65 + n], h, lo);
        g_wb[((0 * 3 + mat) * 64 + n) * 1024 + k0 + k] = h;
        g_wb[((1 * 3 + mat) * 64 + n) * 1024 + k0 + k] = lo;
    }
}

// ---------------------------------------------------------------------------
// Kernel 1: projection GEMM via mma.sync bf16, split-fp32 (3 terms).
// Epilogue: q,k emitted as bf16 hi/lo (tensor-core consumers); v as fp32.
// ---------------------------------------------------------------------------
__global__ __launch_bounds__(256) void projmma_kernel(const float* __restrict__ x)
{
    __shared__ __align__(16) char smA[2][128 * 64];
    __shared__ __align__(16) char smB[2][192 * 64];

    const int tid  = threadIdx.x;
    const int wid  = tid >> 5;
    const int lane = tid & 31;
    const int row0 = blockIdx.x * 128;
    const int r0w  = (wid >> 1) * 32;
    const int c0w  = (wid & 1) * 96;

    const uint32_t aHiB = smem_u32(smA[0]);
    const uint32_t aLoB = smem_u32(smA[1]);
    const uint32_t bHiB = smem_u32(smB[0]);
    const uint32_t bLoB = smem_u32(smB[1]);

    float acc[2][12][4];
#pragma unroll
    for (int mi = 0; mi < 2; mi++)
#pragma unroll
        for (int ni = 0; ni < 12; ni++)
#pragma unroll
            for (int r = 0; r < 4; r++) acc[mi][ni][r] = 0.f;

    const int rA0 = r0w + (lane & 15);
    const int uHiA = lane >> 4;

    for (int c = 0; c < 32; c++) {
        const int k0 = c * 32;
        __syncthreads();
#pragma unroll
        for (int l = 0; l < 4; l++) {
            int row = (tid >> 3) + l * 32;
            int kf  = (tid & 7) * 4;
            float4 xv = *(const float4*)(x + (size_t)(row0 + row) * ND + k0 + kf);
            __nv_bfloat162 h01, h23, l01, l23;
            bf16split(xv.x, h01.x, l01.x); bf16split(xv.y, h01.y, l01.y);
            bf16split(xv.z, h23.x, l23.x); bf16split(xv.w, h23.y, l23.y);
            uint32_t off = swzA(row, kf >> 3) + ((kf & 4) ? 8 : 0);
            uint2 hv = { *(uint32_t*)&h01, *(uint32_t*)&h23 };
            uint2 lv = { *(uint32_t*)&l01, *(uint32_t*)&l23 };
            *(uint2*)(smA[0] + off) = hv;
            *(uint2*)(smA[1] + off) = lv;
        }
#pragma unroll
        for (int l = 0; l < 6; l++) {
            int idx = tid + l * 256;
            int rowhl = idx >> 2;
            int seg = idx & 3;
            int hilo = rowhl >= 192;
            int row = rowhl - hilo * 192;
            uint4 v = *(const uint4*)((const char*)g_wb + (size_t)rowhl * 2048 + k0 * 2 + seg * 16);
            *(uint4*)(smB[hilo] + swzA(row, seg)) = v;
        }
        __syncthreads();

#pragma unroll
        for (int s = 0; s < 2; s++) {
            uint32_t ah[2][4], al[2][4];
#pragma unroll
            for (int mi = 0; mi < 2; mi++) {
                int r = rA0 + mi * 16;
                uint32_t off = swzA(r, 2 * s + uHiA);
                LDSM_X4(ah[mi][0], ah[mi][1], ah[mi][2], ah[mi][3], aHiB + off);
                LDSM_X4(al[mi][0], al[mi][1], al[mi][2], al[mi][3], aLoB + off);
            }
#pragma unroll
            for (int ni = 0; ni < 12; ni++) {
                int rB = c0w + ni * 8 + (lane & 7);
                uint32_t off = swzA(rB, 2 * s + ((lane >> 3) & 1));
                uint32_t bh[2], bl[2];
                LDSM_X2(bh[0], bh[1], bHiB + off);
                LDSM_X2(bl[0], bl[1], bLoB + off);
#pragma unroll
                for (int mi = 0; mi < 2; mi++) {
                    MMA_BF16(acc[mi][ni], ah[mi], bh);
                    MMA_BF16(acc[mi][ni], ah[mi], bl);
                    MMA_BF16(acc[mi][ni], al[mi], bh);
                }
            }
        }
    }

    // Epilogue: q,k -> bf16 hi/lo; v -> fp32
#pragma unroll
    for (int ni = 0; ni < 12; ni++) {
        int cg = c0w + ni * 8 + (lane & 3) * 2;
        int h = cg & 63;
#pragma unroll
        for (int mi = 0; mi < 2; mi++) {
            int r = row0 + r0w + mi * 16 + (lane >> 2);
            if (cg < 128) {
                __nv_bfloat16* dh = (cg < 64) ? g_qh : g_kh;
                __nv_bfloat16* dl = (cg < 64) ? g_ql : g_kl;
                __nv_bfloat162 h2, l2;
                bf16split(acc[mi][ni][0], h2.x, l2.x);
                bf16split(acc[mi][ni][1], h2.y, l2.y);
                *(__nv_bfloat162*)(dh + (size_t)r * NH + h) = h2;
                *(__nv_bfloat162*)(dl + (size_t)r * NH + h) = l2;
                bf16split(acc[mi][ni][2], h2.x, l2.x);
                bf16split(acc[mi][ni][3], h2.y, l2.y);
                *(__nv_bfloat162*)(dh + (size_t)(r + 8) * NH + h) = h2;
                *(__nv_bfloat162*)(dl + (size_t)(r + 8) * NH + h) = l2;
            } else {
                float2 v0 = {acc[mi][ni][0], acc[mi][ni][1]};
                float2 v1 = {acc[mi][ni][2], acc[mi][ni][3]};
                *(float2*)(g_v + (size_t)r * NH + h) = v0;
                *(float2*)(g_v + (size_t)(r + 8) * NH + h) = v1;
            }
        }
    }
}

// ---------------------------------------------------------------------------
// Kernel 2: colsum via HMMA. Block (kt128, chunk, b): S^T tile = K(128) x Q(64)
// per q-tile, 3-term split-bf16. Epilogue: mask/exp on frags, P^T stored as
// bf16 hi/lo, per-row colsum partials.
// A = K [k][h] non-trans ldmatrix; B = Q [q][h] non-trans (contraction h).
// smem: kh 16K | kl 16K | qh 8K | ql 8K = 48K; red overlays qh after use.
// ---------------------------------------------------------------------------
#define CS_KH 0
#define CS_KL 16384
#define CS_QH 32768
#define CS_QL 40960
#define CS_RED 32768            // overlays qh after final q-tile

__global__ __launch_bounds__(256) void colsum_kernel() {
    __shared__ __align__(16) char sm[49152];
    const uint32_t sb = smem_u32(sm);

    const int tid  = threadIdx.x;
    const int wid  = tid >> 5;
    const int lane = tid & 31;
    const int kt = blockIdx.x;
    const int c  = blockIdx.y;
    const int b  = blockIdx.z;
    const int k0 = kt * 128;
    const int wm = wid & 3;          // 32 k-rows per group
    const int wn = wid >> 2;         // 32 q-cols per group

    int qt_begin = 2 * kt; if (8 * c > qt_begin) qt_begin = 8 * c;
    const int qt_end = 8 * c + 8;

    if (qt_begin >= qt_end) {
        if (tid < 128) g_part[(c * NB + b) * NT + k0 + tid] = 0.f;
        return;
    }

    // Load K tile once (128 rows x 64 h bf16, hi+lo), swizzled 128B rows
#pragma unroll
    for (int l = 0; l < 8; l++) {
        int idx = tid + l * 256;
        int hilo = idx >> 10;
        int w = idx & 1023, r = w >> 3, u = w & 7;
        const __nv_bfloat16* src = (hilo ? g_kl : g_kh) + (size_t)(b * NT + k0 + r) * NH + u * 8;
        *(uint4*)(sm + (hilo ? CS_KL : CS_KH) + swz128(r, u)) = *(const uint4*)src;
    }

    float csum[4] = {0.f, 0.f, 0.f, 0.f};

    // Prefetch first Q tile into regs
    uint4 qreg[4];
    {
        const int q0 = qt_begin * 64;
#pragma unroll
        for (int l = 0; l < 4; l++) {
            int idx = tid + l * 256;
            int hilo = idx >> 9;
            int w = idx & 511, r = w >> 3, u = w & 7;
            const __nv_bfloat16* src = (hilo ? g_ql : g_qh) + (size_t)(b * NT + q0 + r) * NH + u * 8;
            qreg[l] = *(const uint4*)src;
        }
    }

    for (int qt = qt_begin; qt < qt_end; qt++) {
        const int q0 = qt * 64;
        __syncthreads();
#pragma unroll
        for (int l = 0; l < 4; l++) {
            int idx = tid + l * 256;
            int hilo = idx >> 9;
            int w = idx & 511, r = w >> 3, u = w & 7;
            *(uint4*)(sm + (hilo ? CS_QL : CS_QH) + swz128(r, u)) = qreg[l];
        }
        __syncthreads();
        if (qt + 1 < qt_end) {
            const int q1 = (qt + 1) * 64;
#pragma unroll
            for (int l = 0; l < 4; l++) {
                int idx = tid + l * 256;
                int hilo = idx >> 9;
                int w = idx & 511, r = w >> 3, u = w & 7;
                const __nv_bfloat16* src = (hilo ? g_ql : g_qh) + (size_t)(b * NT + q1 + r) * NH + u * 8;
                qreg[l] = *(const uint4*)src;
            }
        }

        float acc[2][4][4];
#pragma unroll
        for (int mi = 0; mi < 2; mi++)
#pragma unroll
            for (int ni = 0; ni < 4; ni++)
#pragma unroll
                for (int r = 0; r < 4; r++) acc[mi][ni][r] = 0.f;

#pragma unroll
        for (int s = 0; s < 4; s++) {
            uint32_t ah[2][4], al[2][4];
#pragma unroll
            for (int mi = 0; mi < 2; mi++) {
                int r = wm * 32 + mi * 16 + (lane & 15);
                int u = 2 * s + (lane >> 4);
                LDSM_X4(ah[mi][0], ah[mi][1], ah[mi][2], ah[mi][3], sb + CS_KH + swz128(r, u));
                LDSM_X4(al[mi][0], al[mi][1], al[mi][2], al[mi][3], sb + CS_KL + swz128(r, u));
            }
#pragma unroll
            for (int ni = 0; ni < 4; ni++) {
                int rB = wn * 32 + ni * 8 + (lane & 7);
                int u = 2 * s + ((lane >> 3) & 1);
                uint32_t bh[2], bl[2];
                LDSM_X2(bh[0], bh[1], sb + CS_QH + swz128(rB, u));
                LDSM_X2(bl[0], bl[1], sb + CS_QL + swz128(rB, u));
#pragma unroll
                for (int mi = 0; mi < 2; mi++) {
                    MMA_BF16(acc[mi][ni], ah[mi], bh);
                    MMA_BF16(acc[mi][ni], ah[mi], bl);
                    MMA_BF16(acc[mi][ni], al[mi], bh);
                }
            }
        }

        // Epilogue: mask + exp + csum + P^T bf16 hi/lo stores
        const bool full = (q0 >= k0 + 128);
#pragma unroll
        for (int mi = 0; mi < 2; mi++) {
#pragma unroll
            for (int ni = 0; ni < 4; ni++) {
                int qg = q0 + wn * 32 + ni * 8 + 2 * (lane & 3);
#pragma unroll
                for (int half = 0; half < 2; half++) {
                    int kg = k0 + wm * 32 + mi * 16 + (lane >> 2) + 8 * half;
                    float d0 = acc[mi][ni][2 * half];
                    float d1 = acc[mi][ni][2 * half + 1];
                    float e0 = (full || qg >= kg) ? __expf(d0 * SCALE) : 0.f;
                    float e1 = (full || qg + 1 >= kg) ? __expf(d1 * SCALE) : 0.f;
                    csum[mi * 2 + half] += e0 + e1;
                    __nv_bfloat162 h2, l2;
                    bf16split(e0, h2.x, l2.x);
                    bf16split(e1, h2.y, l2.y);
                    size_t off = (size_t)(b * NT + kg) * NT + qg;
                    *(__nv_bfloat162*)(g_pTh + off) = h2;
                    *(__nv_bfloat162*)(g_pTl + off) = l2;
                }
            }
        }
    }

    // Reduce csum: lanes sharing a k-row (lane&3 quad), then across wn warps
#pragma unroll
    for (int i = 0; i < 4; i++) {
        csum[i] += __shfl_xor_sync(0xFFFFFFFF, csum[i], 1);
        csum[i] += __shfl_xor_sync(0xFFFFFFFF, csum[i], 2);
    }
    __syncthreads();                 // Q smem no longer needed; reuse as red
    float* red = (float*)(sm + CS_RED);
    if ((lane & 3) == 0) {
#pragma unroll
        for (int mi = 0; mi < 2; mi++)
#pragma unroll
            for (int half = 0; half < 2; half++)
                red[wn * 128 + wm * 32 + mi * 16 + (lane >> 2) + 8 * half] = csum[mi * 2 + half];
    }
    __syncthreads();
    if (tid < 128)
        g_part[(c * NB + b) * NT + k0 + tid] = red[tid] + red[128 + tid];
}

// ---------------------------------------------------------------------------
// Kernel 3: v' = v * 1/colsum -> bf16 hi/lo
// ---------------------------------------------------------------------------
__global__ __launch_bounds__(256) void scalev_kernel() {
    int gid = blockIdx.x * 256 + threadIdx.x;
    int token = gid >> 4;
    int h0 = (gid & 15) * 4;
    int b = token >> 11, k = token & 2047;
    float s = g_part[(0 * NB + b) * NT + k] + g_part[(1 * NB + b) * NT + k]
            + g_part[(2 * NB + b) * NT + k] + g_part[(3 * NB + b) * NT + k];
    float rinv = 1.f / s;
    float4 v = *(const float4*)(g_v + (size_t)token * NH + h0);
    __nv_bfloat162 h01, h23, l01, l23;
    bf16split(v.x * rinv, h01.x, l01.x); bf16split(v.y * rinv, h01.y, l01.y);
    bf16split(v.z * rinv, h23.x, l23.x); bf16split(v.w * rinv, h23.y, l23.y);
    uint2 hv = { *(uint32_t*)&h01, *(uint32_t*)&h23 };
    uint2 lv = { *(uint32_t*)&l01, *(uint32_t*)&l23 };
    *(uint2*)(g_v2h + (size_t)token * NH + h0) = hv;
    *(uint2*)(g_v2l + (size_t)token * NH + h0) = lv;
}

// ---------------------------------------------------------------------------
// Kernel 4: out = P_causal @ V' via HMMA with .trans ldmatrix.
// A[q][k] from P^T[k][q] (trans x4); B[h][k] from V'[k][h] (trans x2).
// Block: 64 q-rows x 64 h. Warp tile 16q x 32h. Register-prefetch k-chunks.
// ---------------------------------------------------------------------------
__global__ __launch_bounds__(256) void out_kernel(float* __restrict__ out) {
    __shared__ __align__(16) char smP[2][64 * 128];   // [hilo][k][q] bf16
    __shared__ __align__(16) char smV[2][64 * 128];   // [hilo][k][h] bf16

    const int tid  = threadIdx.x;
    const int wid  = tid >> 5;
    const int lane = tid & 31;
    const int qt = (NTILES - 1) - blockIdx.x;        // longest blocks first
    const int b  = blockIdx.y;
    const int q0 = qt * 64;
    const int wm = wid >> 1;         // 16 q-rows per group
    const int wn = wid & 1;          // 32 h per group

    const uint32_t pHiB = smem_u32(smP[0]);
    const uint32_t pLoB = smem_u32(smP[1]);
    const uint32_t vHiB = smem_u32(smV[0]);
    const uint32_t vLoB = smem_u32(smV[1]);

    float acc[4][4];
#pragma unroll
    for (int ni = 0; ni < 4; ni++)
#pragma unroll
        for (int r = 0; r < 4; r++) acc[ni][r] = 0.f;

    uint4 pP[4], pV[4];
#define OUT_LOAD(KT)                                                            \
    do {                                                                        \
        const int _k0 = (KT) * 64;                                              \
        _Pragma("unroll")                                                       \
        for (int l = 0; l < 4; l++) {                                           \
            int idx = tid + l * 256;                                            \
            int hilo = idx >> 9;                                                \
            int w = idx & 511, r = w >> 3, u = w & 7;                           \
            const __nv_bfloat16* sp = (hilo ? g_pTl : g_pTh)                    \
                + (size_t)(b * NT + _k0 + r) * NT + q0 + u * 8;                 \
            const __nv_bfloat16* sv = (hilo ? g_v2l : g_v2h)                    \
                + (size_t)(b * NT + _k0 + r) * NH + u * 8;                      \
            pP[l] = *(const uint4*)sp;                                          \
            pV[l] = *(const uint4*)sv;                                          \
        }                                                                       \
    } while (0)

    OUT_LOAD(0);

    for (int kt = 0; kt <= qt; kt++) {
        __syncthreads();
#pragma unroll
        for (int l = 0; l < 4; l++) {
            int idx = tid + l * 256;
            int hilo = idx >> 9;
            int w = idx & 511, r = w >> 3, u = w & 7;
            *(uint4*)(smP[hilo] + swz128(r, u)) = pP[l];
            *(uint4*)(smV[hilo] + swz128(r, u)) = pV[l];
        }
        __syncthreads();
        if (kt < qt) OUT_LOAD(kt + 1);

#pragma unroll
        for (int s = 0; s < 4; s++) {
            // A frag (q rows) via trans-ldmatrix from P^T[k][q]
            int rA = s * 16 + (lane & 7) + 8 * (lane >> 4);
            int uA = wm * 2 + ((lane >> 3) & 1);
            uint32_t ah[4], al[4];
            LDSM_X4_T(ah[0], ah[1], ah[2], ah[3], pHiB + swz128(rA, uA));
            LDSM_X4_T(al[0], al[1], al[2], al[3], pLoB + swz128(rA, uA));
#pragma unroll
            for (int ni = 0; ni < 4; ni++) {
                int rB = s * 16 + (lane & 7) + 8 * ((lane >> 3) & 1);
                int uB = wn * 4 + ni;
                uint32_t bh[2], bl[2];
                LDSM_X2_T(bh[0], bh[1], vHiB + swz128(rB, uB));
                LDSM_X2_T(bl[0], bl[1], vLoB + swz128(rB, uB));
                MMA_BF16(acc[ni], ah, bh);
                MMA_BF16(acc[ni], ah, bl);
                MMA_BF16(acc[ni], al, bh);
            }
        }
    }

    // Epilogue: D frags -> out fp32
#pragma unroll
    for (int ni = 0; ni < 4; ni++) {
        int h = wn * 32 + ni * 8 + 2 * (lane & 3);
        int q = q0 + wm * 16 + (lane >> 2);
        float2 v0 = {acc[ni][0], acc[ni][1]};
        float2 v1 = {acc[ni][2], acc[ni][3]};
        *(float2*)(out + (size_t)(b * NT + q) * NH + h) = v0;
        *(float2*)(out + (size_t)(b * NT + q + 8) * NH + h) = v1;
    }
#undef OUT_LOAD
}

// ---------------------------------------------------------------------------
// Launch (graph-capturable, allocation-free, atomic-free -> deterministic).
// Input order per metadata: x, Wk, Wq, Wv.
// ---------------------------------------------------------------------------
extern "C" void kernel_launch(void* const* d_in, const int* in_sizes, int n_in,
                              void* d_out, int out_size) {
    const float* x  = (const float*)d_in[0];
    const float* Wk = (const float*)d_in[1];
    const float* Wq = (const float*)d_in[2];
    const float* Wv = (const float*)d_in[3];
    float* out = (float*)d_out;

    wconv_kernel<<<48, 256>>>(Wq, Wk, Wv);
    projmma_kernel<<<(NB * NT) / 128, 256>>>(x);
    colsum_kernel<<<dim3(KT128, QCHUNK, NB), 256>>>();
    scalev_kernel<<<(NB * NT * NH / 4) / 256, 256>>>();
    out_kernel<<<dim3(NTILES, NB), 256>>>(out);
}

// round 13
// speedup vs baseline: 6.4177x; 1.1684x over previous
#include <cuda_runtime.h>
#include <cuda_bf16.h>
#include <math.h>
#include <stdint.h>

// Problem constants
#define NB 8
#define NT 2048
#define ND 1024
#define NH 64
#define SCALE 0.125f            // H^-0.5 = 1/8
#define NTILES (NT / 64)        // 32 q-tiles (64 rows)
#define KT128  (NT / 128)       // 16 k-tiles (128 cols) for colsum
#define QCHUNK 4                // q-chunks per k-tile (8 q-tiles each)

// Scratch (allocation-free: __device__ globals)
__device__ float g_v[NB * NT * NH];                    // V fp32 (from proj)
__device__ float g_part[QCHUNK * NB * NT];             // partial column sums
__device__ __nv_bfloat16 g_qh[NB * NT * NH];           // Q hi/lo bf16
__device__ __nv_bfloat16 g_ql[NB * NT * NH];
__device__ __nv_bfloat16 g_kh[NB * NT * NH];           // K hi/lo bf16
__device__ __nv_bfloat16 g_kl[NB * NT * NH];
__device__ __nv_bfloat16 g_v2h[NB * NT * NH];          // V' = V/colsum hi/lo
__device__ __nv_bfloat16 g_v2l[NB * NT * NH];
__device__ __nv_bfloat16 g_pTh[(size_t)NB * NT * NT];  // P^T hi: [b][k][q] 67MB
__device__ __nv_bfloat16 g_pTl[(size_t)NB * NT * NT];  // P^T lo
// W transposed + split: [hilo][mat][n=64][k=1024] bf16
__device__ __nv_bfloat16 g_wb[2 * 3 * 64 * 1024];

// ---------------------------------------------------------------------------
// Helpers: legacy tensor path (compute_103-legal): ldmatrix + mma.sync bf16,
// plus cp.async (Ampere+) for async gmem->smem pipelines.
// ---------------------------------------------------------------------------
__device__ __forceinline__ uint32_t smem_u32(const void* p) {
    uint32_t a;
    asm("{ .reg .u64 t; cvta.to.shared.u64 t, %1; cvt.u32.u64 %0, t; }"
        : "=r"(a) : "l"(p));
    return a;
}
#define LDSM_X4(r0, r1, r2, r3, a)                                              \
    asm volatile("ldmatrix.sync.aligned.m8n8.x4.shared.b16 {%0,%1,%2,%3}, [%4];" \
                 : "=r"(r0), "=r"(r1), "=r"(r2), "=r"(r3) : "r"(a))
#define LDSM_X2(r0, r1, a)                                                      \
    asm volatile("ldmatrix.sync.aligned.m8n8.x2.shared.b16 {%0,%1}, [%2];"      \
                 : "=r"(r0), "=r"(r1) : "r"(a))
#define LDSM_X4_T(r0, r1, r2, r3, a)                                            \
    asm volatile("ldmatrix.sync.aligned.m8n8.x4.trans.shared.b16 {%0,%1,%2,%3}, [%4];" \
                 : "=r"(r0), "=r"(r1), "=r"(r2), "=r"(r3) : "r"(a))
#define LDSM_X2_T(r0, r1, a)                                                    \
    asm volatile("ldmatrix.sync.aligned.m8n8.x2.trans.shared.b16 {%0,%1}, [%2];" \
                 : "=r"(r0), "=r"(r1) : "r"(a))
#define MMA_BF16(d, a, b)                                                       \
    asm volatile("mma.sync.aligned.m16n8k16.row.col.f32.bf16.bf16.f32 "         \
                 "{%0,%1,%2,%3}, {%4,%5,%6,%7}, {%8,%9}, {%0,%1,%2,%3};"        \
                 : "+f"((d)[0]), "+f"((d)[1]), "+f"((d)[2]), "+f"((d)[3])       \
                 : "r"((a)[0]), "r"((a)[1]), "r"((a)[2]), "r"((a)[3]),          \
                   "r"((b)[0]), "r"((b)[1]))

__device__ __forceinline__ void cp_async16(uint32_t smem, const void* g) {
    asm volatile("cp.async.cg.shared.global [%0], [%1], 16;"
                 :: "r"(smem), "l"(g) : "memory");
}
#define CP_COMMIT() asm volatile("cp.async.commit_group;" ::: "memory")
#define CP_WAIT(N)  asm volatile("cp.async.wait_group " #N ";" ::: "memory")

// Swizzles (16B units). 64B rows (proj) / 128B rows (colsum, out).
__device__ __forceinline__ uint32_t swzA(int r, int u) {
    return (uint32_t)(r * 64 + ((u ^ ((r >> 1) & 3)) << 4));
}
__device__ __forceinline__ uint32_t swz128(int r, int u) {
    return (uint32_t)(r * 128 + ((u ^ (r & 7)) << 4));
}
__device__ __forceinline__ void bf16split(float f, __nv_bfloat16& h, __nv_bfloat16& l) {
    h = __float2bfloat16_rn(f);
    l = __float2bfloat16_rn(f - __bfloat162float(h));
}

// ---------------------------------------------------------------------------
// Kernel 0: W -> transposed, bf16 hi/lo split, B layout [hilo][mat][n][k].
// ---------------------------------------------------------------------------
__global__ __launch_bounds__(256) void wconv_kernel(
    const float* __restrict__ Wq, const float* __restrict__ Wk,
    const float* __restrict__ Wv)
{
    __shared__ float tile[64 * 65];
    const int mat = blockIdx.x >> 4;
    const int k0  = (blockIdx.x & 15) * 64;
    const float* W = (mat == 0) ? Wq : (mat == 1) ? Wk : Wv;
    const int tid = threadIdx.x;

#pragma unroll
    for (int l = 0; l < 16; l++) {
        int idx = tid + l * 256;
        int k = idx >> 6, n = idx & 63;
        tile[k * 65 + n] = W[(k0 + k) * NH + n];
    }
    __syncthreads();
#pragma unroll
    for (int l = 0; l < 16; l++) {
        int idx = tid + l * 256;
        int n = idx >> 6, k = idx & 63;
        __nv_bfloat16 h, lo;
        bf16split(tile[k * 65 + n], h, lo);
        g_wb[((0 * 3 + mat) * 64 + n) * 1024 + k0 + k] = h;
        g_wb[((1 * 3 + mat) * 64 + n) * 1024 + k0 + k] = lo;
    }
}

// ---------------------------------------------------------------------------
// Kernel 1: projection GEMM via mma.sync bf16, split-fp32 (3 terms).
// Pipelined: A(x) register-prefetched one chunk ahead (cvt at STS time);
// B(W) double-buffered via cp.async, committed one chunk ahead.
// Dynamic smem 64KB: A hi 8K | A lo 8K | B stage0 24K | B stage1 24K.
// ---------------------------------------------------------------------------
#define PJ_ALO 8192
#define PJ_B(s) (16384 + (s) * 24576)
#define PJ_SMEM 65536

__global__ __launch_bounds__(256) void projmma_kernel(const float* __restrict__ x)
{
    extern __shared__ __align__(16) char sm[];
    const uint32_t sb = smem_u32(sm);

    const int tid  = threadIdx.x;
    const int wid  = tid >> 5;
    const int lane = tid & 31;
    const int row0 = blockIdx.x * 128;
    const int r0w  = (wid >> 1) * 32;
    const int c0w  = (wid & 1) * 96;

    float acc[2][12][4];
#pragma unroll
    for (int mi = 0; mi < 2; mi++)
#pragma unroll
        for (int ni = 0; ni < 12; ni++)
#pragma unroll
            for (int r = 0; r < 4; r++) acc[mi][ni][r] = 0.f;

    const int rA0 = r0w + (lane & 15);
    const int uHiA = lane >> 4;
    const int ldRow = (tid >> 3);             // A load: rows ldRow + 32*l
    const int ldKf  = (tid & 7) * 4;

    // B cp.async indexing (6 x 16B per thread per chunk)
    const char* bSrcBase[6];
    uint32_t bDstOff[6];
#pragma unroll
    for (int l = 0; l < 6; l++) {
        int idx = tid + l * 256;
        int rowhl = idx >> 2;
        int seg = idx & 3;
        int hilo = rowhl >= 192;
        int row = rowhl - hilo * 192;
        bSrcBase[l] = (const char*)g_wb + (size_t)rowhl * 2048 + seg * 16;
        bDstOff[l] = (uint32_t)(hilo * 12288) + swzA(row, seg);
    }

    // Prologue: A(0) into regs; B(0) -> stage 0
    float4 xv[4];
#pragma unroll
    for (int l = 0; l < 4; l++)
        xv[l] = *(const float4*)(x + (size_t)(row0 + ldRow + l * 32) * ND + 0 + ldKf);
#pragma unroll
    for (int l = 0; l < 6; l++)
        cp_async16(sb + PJ_B(0) + bDstOff[l], bSrcBase[l]);
    CP_COMMIT();

    for (int c = 0; c < 32; c++) {
        const int s = c & 1;
        __syncthreads();                     // MMA(c-1) done reading smA / B(s^1)
        // STS A(c) from prefetched regs, with bf16 hi/lo split
#pragma unroll
        for (int l = 0; l < 4; l++) {
            int row = ldRow + l * 32;
            __nv_bfloat162 h01, h23, l01, l23;
            bf16split(xv[l].x, h01.x, l01.x); bf16split(xv[l].y, h01.y, l01.y);
            bf16split(xv[l].z, h23.x, l23.x); bf16split(xv[l].w, h23.y, l23.y);
            uint32_t off = swzA(row, ldKf >> 3) + ((ldKf & 4) ? 8 : 0);
            uint2 hv = { *(uint32_t*)&h01, *(uint32_t*)&h23 };
            uint2 lv = { *(uint32_t*)&l01, *(uint32_t*)&l23 };
            *(uint2*)(sm + off) = hv;
            *(uint2*)(sm + PJ_ALO + off) = lv;
        }
        // Issue B(c+1) into the other stage (chunk stride = 32 bf16 = 64 bytes)
        if (c < 31) {
#pragma unroll
            for (int l = 0; l < 6; l++)
                cp_async16(sb + PJ_B(s ^ 1) + bDstOff[l],
                           bSrcBase[l] + (size_t)(c + 1) * 64);
            CP_COMMIT();
            CP_WAIT(1);                      // B(c) complete
        } else {
            CP_WAIT(0);
        }
        __syncthreads();                     // A STS + B(c) visible
        // Prefetch A(c+1) into regs (hidden under MMA)
        if (c < 31) {
#pragma unroll
            for (int l = 0; l < 4; l++)
                xv[l] = *(const float4*)(x + (size_t)(row0 + ldRow + l * 32) * ND
                                           + (c + 1) * 32 + ldKf);
        }

        const uint32_t bSt = sb + PJ_B(s);
#pragma unroll
        for (int st = 0; st < 2; st++) {
            uint32_t ah[2][4], al[2][4];
#pragma unroll
            for (int mi = 0; mi < 2; mi++) {
                int r = rA0 + mi * 16;
                uint32_t off = swzA(r, 2 * st + uHiA);
                LDSM_X4(ah[mi][0], ah[mi][1], ah[mi][2], ah[mi][3], sb + off);
                LDSM_X4(al[mi][0], al[mi][1], al[mi][2], al[mi][3], sb + PJ_ALO + off);
            }
#pragma unroll
            for (int ni = 0; ni < 12; ni++) {
                int rB = c0w + ni * 8 + (lane & 7);
                uint32_t off = swzA(rB, 2 * st + ((lane >> 3) & 1));
                uint32_t bh[2], bl[2];
                LDSM_X2(bh[0], bh[1], bSt + off);
                LDSM_X2(bl[0], bl[1], bSt + 12288 + off);
#pragma unroll
                for (int mi = 0; mi < 2; mi++) {
                    MMA_BF16(acc[mi][ni], ah[mi], bh);
                    MMA_BF16(acc[mi][ni], ah[mi], bl);
                    MMA_BF16(acc[mi][ni], al[mi], bh);
                }
            }
        }
    }

    // Epilogue: q,k -> bf16 hi/lo; v -> fp32
#pragma unroll
    for (int ni = 0; ni < 12; ni++) {
        int cg = c0w + ni * 8 + (lane & 3) * 2;
        int h = cg & 63;
#pragma unroll
        for (int mi = 0; mi < 2; mi++) {
            int r = row0 + r0w + mi * 16 + (lane >> 2);
            if (cg < 128) {
                __nv_bfloat16* dh = (cg < 64) ? g_qh : g_kh;
                __nv_bfloat16* dl = (cg < 64) ? g_ql : g_kl;
                __nv_bfloat162 h2, l2;
                bf16split(acc[mi][ni][0], h2.x, l2.x);
                bf16split(acc[mi][ni][1], h2.y, l2.y);
                *(__nv_bfloat162*)(dh + (size_t)r * NH + h) = h2;
                *(__nv_bfloat162*)(dl + (size_t)r * NH + h) = l2;
                bf16split(acc[mi][ni][2], h2.x, l2.x);
                bf16split(acc[mi][ni][3], h2.y, l2.y);
                *(__nv_bfloat162*)(dh + (size_t)(r + 8) * NH + h) = h2;
                *(__nv_bfloat162*)(dl + (size_t)(r + 8) * NH + h) = l2;
            } else {
                float2 v0 = {acc[mi][ni][0], acc[mi][ni][1]};
                float2 v1 = {acc[mi][ni][2], acc[mi][ni][3]};
                *(float2*)(g_v + (size_t)r * NH + h) = v0;
                *(float2*)(g_v + (size_t)(r + 8) * NH + h) = v1;
            }
        }
    }
}

// ---------------------------------------------------------------------------
// Kernel 2: colsum via HMMA (unchanged from R10-passing version).
// ---------------------------------------------------------------------------
#define CS_KH 0
#define CS_KL 16384
#define CS_QH 32768
#define CS_QL 40960
#define CS_RED 32768

__global__ __launch_bounds__(256) void colsum_kernel() {
    __shared__ __align__(16) char sm[49152];
    const uint32_t sb = smem_u32(sm);

    const int tid  = threadIdx.x;
    const int wid  = tid >> 5;
    const int lane = tid & 31;
    const int kt = blockIdx.x;
    const int c  = blockIdx.y;
    const int b  = blockIdx.z;
    const int k0 = kt * 128;
    const int wm = wid & 3;
    const int wn = wid >> 2;

    int qt_begin = 2 * kt; if (8 * c > qt_begin) qt_begin = 8 * c;
    const int qt_end = 8 * c + 8;

    if (qt_begin >= qt_end) {
        if (tid < 128) g_part[(c * NB + b) * NT + k0 + tid] = 0.f;
        return;
    }

#pragma unroll
    for (int l = 0; l < 8; l++) {
        int idx = tid + l * 256;
        int hilo = idx >> 10;
        int w = idx & 1023, r = w >> 3, u = w & 7;
        const __nv_bfloat16* src = (hilo ? g_kl : g_kh) + (size_t)(b * NT + k0 + r) * NH + u * 8;
        *(uint4*)(sm + (hilo ? CS_KL : CS_KH) + swz128(r, u)) = *(const uint4*)src;
    }

    float csum[4] = {0.f, 0.f, 0.f, 0.f};

    uint4 qreg[4];
    {
        const int q0 = qt_begin * 64;
#pragma unroll
        for (int l = 0; l < 4; l++) {
            int idx = tid + l * 256;
            int hilo = idx >> 9;
            int w = idx & 511, r = w >> 3, u = w & 7;
            const __nv_bfloat16* src = (hilo ? g_ql : g_qh) + (size_t)(b * NT + q0 + r) * NH + u * 8;
            qreg[l] = *(const uint4*)src;
        }
    }

    for (int qt = qt_begin; qt < qt_end; qt++) {
        const int q0 = qt * 64;
        __syncthreads();
#pragma unroll
        for (int l = 0; l < 4; l++) {
            int idx = tid + l * 256;
            int hilo = idx >> 9;
            int w = idx & 511, r = w >> 3, u = w & 7;
            *(uint4*)(sm + (hilo ? CS_QL : CS_QH) + swz128(r, u)) = qreg[l];
        }
        __syncthreads();
        if (qt + 1 < qt_end) {
            const int q1 = (qt + 1) * 64;
#pragma unroll
            for (int l = 0; l < 4; l++) {
                int idx = tid + l * 256;
                int hilo = idx >> 9;
                int w = idx & 511, r = w >> 3, u = w & 7;
                const __nv_bfloat16* src = (hilo ? g_ql : g_qh) + (size_t)(b * NT + q1 + r) * NH + u * 8;
                qreg[l] = *(const uint4*)src;
            }
        }

        float acc[2][4][4];
#pragma unroll
        for (int mi = 0; mi < 2; mi++)
#pragma unroll
            for (int ni = 0; ni < 4; ni++)
#pragma unroll
                for (int r = 0; r < 4; r++) acc[mi][ni][r] = 0.f;

#pragma unroll
        for (int s = 0; s < 4; s++) {
            uint32_t ah[2][4], al[2][4];
#pragma unroll
            for (int mi = 0; mi < 2; mi++) {
                int r = wm * 32 + mi * 16 + (lane & 15);
                int u = 2 * s + (lane >> 4);
                LDSM_X4(ah[mi][0], ah[mi][1], ah[mi][2], ah[mi][3], sb + CS_KH + swz128(r, u));
                LDSM_X4(al[mi][0], al[mi][1], al[mi][2], al[mi][3], sb + CS_KL + swz128(r, u));
            }
#pragma unroll
            for (int ni = 0; ni < 4; ni++) {
                int rB = wn * 32 + ni * 8 + (lane & 7);
                int u = 2 * s + ((lane >> 3) & 1);
                uint32_t bh[2], bl[2];
                LDSM_X2(bh[0], bh[1], sb + CS_QH + swz128(rB, u));
                LDSM_X2(bl[0], bl[1], sb + CS_QL + swz128(rB, u));
#pragma unroll
                for (int mi = 0; mi < 2; mi++) {
                    MMA_BF16(acc[mi][ni], ah[mi], bh);
                    MMA_BF16(acc[mi][ni], ah[mi], bl);
                    MMA_BF16(acc[mi][ni], al[mi], bh);
                }
            }
        }

        const bool full = (q0 >= k0 + 128);
#pragma unroll
        for (int mi = 0; mi < 2; mi++) {
#pragma unroll
            for (int ni = 0; ni < 4; ni++) {
                int qg = q0 + wn * 32 + ni * 8 + 2 * (lane & 3);
#pragma unroll
                for (int half = 0; half < 2; half++) {
                    int kg = k0 + wm * 32 + mi * 16 + (lane >> 2) + 8 * half;
                    float d0 = acc[mi][ni][2 * half];
                    float d1 = acc[mi][ni][2 * half + 1];
                    float e0 = (full || qg >= kg) ? __expf(d0 * SCALE) : 0.f;
                    float e1 = (full || qg + 1 >= kg) ? __expf(d1 * SCALE) : 0.f;
                    csum[mi * 2 + half] += e0 + e1;
                    __nv_bfloat162 h2, l2;
                    bf16split(e0, h2.x, l2.x);
                    bf16split(e1, h2.y, l2.y);
                    size_t off = (size_t)(b * NT + kg) * NT + qg;
                    *(__nv_bfloat162*)(g_pTh + off) = h2;
                    *(__nv_bfloat162*)(g_pTl + off) = l2;
                }
            }
        }
    }

#pragma unroll
    for (int i = 0; i < 4; i++) {
        csum[i] += __shfl_xor_sync(0xFFFFFFFF, csum[i], 1);
        csum[i] += __shfl_xor_sync(0xFFFFFFFF, csum[i], 2);
    }
    __syncthreads();
    float* red = (float*)(sm + CS_RED);
    if ((lane & 3) == 0) {
#pragma unroll
        for (int mi = 0; mi < 2; mi++)
#pragma unroll
            for (int half = 0; half < 2; half++)
                red[wn * 128 + wm * 32 + mi * 16 + (lane >> 2) + 8 * half] = csum[mi * 2 + half];
    }
    __syncthreads();
    if (tid < 128)
        g_part[(c * NB + b) * NT + k0 + tid] = red[tid] + red[128 + tid];
}

// ---------------------------------------------------------------------------
// Kernel 3: v' = v * 1/colsum -> bf16 hi/lo
// ---------------------------------------------------------------------------
__global__ __launch_bounds__(256) void scalev_kernel() {
    int gid = blockIdx.x * 256 + threadIdx.x;
    int token = gid >> 4;
    int h0 = (gid & 15) * 4;
    int b = token >> 11, k = token & 2047;
    float s = g_part[(0 * NB + b) * NT + k] + g_part[(1 * NB + b) * NT + k]
            + g_part[(2 * NB + b) * NT + k] + g_part[(3 * NB + b) * NT + k];
    float rinv = 1.f / s;
    float4 v = *(const float4*)(g_v + (size_t)token * NH + h0);
    __nv_bfloat162 h01, h23, l01, l23;
    bf16split(v.x * rinv, h01.x, l01.x); bf16split(v.y * rinv, h01.y, l01.y);
    bf16split(v.z * rinv, h23.x, l23.x); bf16split(v.w * rinv, h23.y, l23.y);
    uint2 hv = { *(uint32_t*)&h01, *(uint32_t*)&h23 };
    uint2 lv = { *(uint32_t*)&l01, *(uint32_t*)&l23 };
    *(uint2*)(g_v2h + (size_t)token * NH + h0) = hv;
    *(uint2*)(g_v2l + (size_t)token * NH + h0) = lv;
}

// ---------------------------------------------------------------------------
// Kernel 4: out = P_causal @ V' via HMMA, 2-stage cp.async pipeline.
// Dynamic smem 64KB: stage s at s*32768: PH 8K | PL 8K | VH 8K | VL 8K.
// ---------------------------------------------------------------------------
#define OUT_SMEM 65536

__global__ __launch_bounds__(256, 2) void out_kernel(float* __restrict__ out) {
    extern __shared__ __align__(16) char sm[];
    const uint32_t sb = smem_u32(sm);

    const int tid  = threadIdx.x;
    const int wid  = tid >> 5;
    const int lane = tid & 31;
    const int qt = (NTILES - 1) - blockIdx.x;        // longest blocks first
    const int b  = blockIdx.y;
    const int q0 = qt * 64;
    const int wm = wid >> 1;
    const int wn = wid & 1;

    float acc[4][4];
#pragma unroll
    for (int ni = 0; ni < 4; ni++)
#pragma unroll
        for (int r = 0; r < 4; r++) acc[ni][r] = 0.f;

    // cp.async copy of one (P,V) tile pair into stage s
    auto issue_tile = [&](int kt, int s) {
        const int k0 = kt * 64;
#pragma unroll
        for (int l = 0; l < 8; l++) {
            int idx = tid + l * 256;
            int arr = idx >> 9;                      // 0:PH 1:PL 2:VH 3:VL
            int w = idx & 511, r = w >> 3, u = w & 7;
            const __nv_bfloat16* src;
            if (arr == 0)      src = g_pTh + (size_t)(b * NT + k0 + r) * NT + q0 + u * 8;
            else if (arr == 1) src = g_pTl + (size_t)(b * NT + k0 + r) * NT + q0 + u * 8;
            else if (arr == 2) src = g_v2h + (size_t)(b * NT + k0 + r) * NH + u * 8;
            else               src = g_v2l + (size_t)(b * NT + k0 + r) * NH + u * 8;
            cp_async16(sb + s * 32768 + arr * 8192 + swz128(r, u), src);
        }
        CP_COMMIT();
    };

    issue_tile(0, 0);

    for (int kt = 0; kt <= qt; kt++) {
        const int s = kt & 1;
        if (kt < qt) { issue_tile(kt + 1, s ^ 1); CP_WAIT(1); }
        else         { CP_WAIT(0); }
        __syncthreads();                 // stage s ready for all threads

        const uint32_t pHiB = sb + s * 32768;
        const uint32_t pLoB = pHiB + 8192;
        const uint32_t vHiB = pHiB + 16384;
        const uint32_t vLoB = pHiB + 24576;

#pragma unroll
        for (int st = 0; st < 4; st++) {
            int rA = st * 16 + (lane & 7) + 8 * (lane >> 4);
            int uA = wm * 2 + ((lane >> 3) & 1);
            uint32_t ah[4], al[4];
            LDSM_X4_T(ah[0], ah[1], ah[2], ah[3], pHiB + swz128(rA, uA));
            LDSM_X4_T(al[0], al[1], al[2], al[3], pLoB + swz128(rA, uA));
#pragma unroll
            for (int ni = 0; ni < 4; ni++) {
                int rB = st * 16 + (lane & 7) + 8 * ((lane >> 3) & 1);
                int uB = wn * 4 + ni;
                uint32_t bh[2], bl[2];
                LDSM_X2_T(bh[0], bh[1], vHiB + swz128(rB, uB));
                LDSM_X2_T(bl[0], bl[1], vLoB + swz128(rB, uB));
                MMA_BF16(acc[ni], ah, bh);
                MMA_BF16(acc[ni], ah, bl);
                MMA_BF16(acc[ni], al, bh);
            }
        }
        __syncthreads();                 // done reading stage s before reuse
    }

    // Epilogue: D frags -> out fp32
#pragma unroll
    for (int ni = 0; ni < 4; ni++) {
        int h = wn * 32 + ni * 8 + 2 * (lane & 3);
        int q = q0 + wm * 16 + (lane >> 2);
        float2 v0 = {acc[ni][0], acc[ni][1]};
        float2 v1 = {acc[ni][2], acc[ni][3]};
        *(float2*)(out + (size_t)(b * NT + q) * NH + h) = v0;
        *(float2*)(out + (size_t)(b * NT + q + 8) * NH + h) = v1;
    }
}

// ---------------------------------------------------------------------------
// Launch (graph-capturable, allocation-free, atomic-free -> deterministic).
// Input order per metadata: x, Wk, Wq, Wv.
// ---------------------------------------------------------------------------
extern "C" void kernel_launch(void* const* d_in, const int* in_sizes, int n_in,
                              void* d_out, int out_size) {
    const float* x  = (const float*)d_in[0];
    const float* Wk = (const float*)d_in[1];
    const float* Wq = (const float*)d_in[2];
    const float* Wv = (const float*)d_in[3];
    float* out = (float*)d_out;

    cudaFuncSetAttribute(projmma_kernel,
                         cudaFuncAttributeMaxDynamicSharedMemorySize, PJ_SMEM);
    cudaFuncSetAttribute(out_kernel,
                         cudaFuncAttributeMaxDynamicSharedMemorySize, OUT_SMEM);

    wconv_kernel<<<48, 256>>>(Wq, Wk, Wv);
    projmma_kernel<<<(NB * NT) / 128, 256, PJ_SMEM>>>(x);
    colsum_kernel<<<dim3(KT128, QCHUNK, NB), 256>>>();
    scalev_kernel<<<(NB * NT * NH / 4) / 256, 256>>>();
    out_kernel<<<dim3(NTILES, NB), 256, OUT_SMEM>>>(out);
}